// round 1
// baseline (speedup 1.0000x reference)
#include <cuda_runtime.h>

// EmbeddingBlock: out = swish( [emb[z[s]] | emb[z[d]] | e_rbf@edge_W^T] @ dense_W^T + b )
//
// Factorization: only VOCAB distinct embedding rows exist, so the two 128-wide
// GEMM slabs collapse into lookup tables:
//   P1[v]    = emb[v] @ dense_W[:, 0:128]^T          (VOCAB x 272)
//   P2[v]    = emb[v] @ dense_W[:, 128:256]^T        (VOCAB x 272)
//   W3eff[r] = sum_i edge_W[i][r] * dense_W[:,256+i] (16 x 272)
//   P12[vs][vd] = P1[vs] + P2[vd] + b                (VOCAB^2 x 272, ~10.9 MB)
// Per edge: out = swish( P12[z[s]*V + z[d]] + e_rbf[e] @ W3eff )  -> memory bound.

#define D    128
#define RBF  16
#define CAT  272
#define J4   (CAT / 4)   // 68 float4 per row
#define VMAX 128

// Scratch (module-static device globals; no runtime allocation)
__device__ float4 g_W3[RBF * J4];                     // [r][j4]
__device__ float  g_P1[VMAX * CAT];
__device__ float  g_P2[VMAX * CAT];
__device__ float4 g_P12[VMAX * VMAX * J4];            // ~17.8 MB reserved, 10.9 MB used

// ---------------------------------------------------------------------------
// Kernel 1: build P1, P2 (blocks 0..V-1) and W3eff (blocks V..V+15)
// ---------------------------------------------------------------------------
__global__ void prep_tables(const float* __restrict__ emb,
                            const float* __restrict__ dW,
                            const float* __restrict__ eW,
                            int V) {
    const int bid = blockIdx.x;
    const int j   = threadIdx.x;          // 0..271  (output column)
    if (bid < V) {
        __shared__ float sh_emb[D];
        if (j < D) sh_emb[j] = emb[bid * D + j];
        __syncthreads();
        const float4* wrow = reinterpret_cast<const float4*>(dW + (long long)j * CAT);
        float a1 = 0.f, a2 = 0.f;
#pragma unroll
        for (int k4 = 0; k4 < D / 4; ++k4) {
            float4 t = wrow[k4];
            a1 = fmaf(sh_emb[4 * k4 + 0], t.x, a1);
            a1 = fmaf(sh_emb[4 * k4 + 1], t.y, a1);
            a1 = fmaf(sh_emb[4 * k4 + 2], t.z, a1);
            a1 = fmaf(sh_emb[4 * k4 + 3], t.w, a1);
        }
#pragma unroll
        for (int k4 = 0; k4 < D / 4; ++k4) {
            float4 t = wrow[D / 4 + k4];
            a2 = fmaf(sh_emb[4 * k4 + 0], t.x, a2);
            a2 = fmaf(sh_emb[4 * k4 + 1], t.y, a2);
            a2 = fmaf(sh_emb[4 * k4 + 2], t.z, a2);
            a2 = fmaf(sh_emb[4 * k4 + 3], t.w, a2);
        }
        g_P1[bid * CAT + j] = a1;
        g_P2[bid * CAT + j] = a2;
    } else {
        const int r = bid - V;             // 0..15
        float a = 0.f;
#pragma unroll
        for (int i = 0; i < RBF; ++i)
            a = fmaf(eW[i * RBF + r], dW[(long long)j * CAT + 2 * D + i], a);
        reinterpret_cast<float*>(g_W3)[r * CAT + j] = a;
    }
}

// ---------------------------------------------------------------------------
// Kernel 2: P12[vs*V+vd] = P1[vs] + P2[vd] + b
// ---------------------------------------------------------------------------
__global__ void prep_pairs(const float* __restrict__ b, int V) {
    const int bid = blockIdx.x;            // vs*V + vd
    const int vs  = bid / V;
    const int vd  = bid - vs * V;
    const int j   = threadIdx.x;           // 0..271
    float val = g_P1[vs * CAT + j] + g_P2[vd * CAT + j] + b[j];
    reinterpret_cast<float*>(g_P12)[(long long)bid * CAT + j] = val;
}

// ---------------------------------------------------------------------------
// Kernel 3: per-edge epilogue. block = (68, 4): x = float4 column, y = edge slot.
// W3eff lives in 64 registers per thread (persistent grid amortizes the load).
// ---------------------------------------------------------------------------
__global__ void __launch_bounds__(272, 2)
edge_main(const float* __restrict__ e_rbf, const int* __restrict__ z,
          const int* __restrict__ nbr, float* __restrict__ out,
          int E, int V) {
    const int tx = threadIdx.x;            // 0..67
    const int ty = threadIdx.y;            // 0..3

    float4 w[RBF];
#pragma unroll
    for (int r = 0; r < RBF; ++r) w[r] = g_W3[r * J4 + tx];

    __shared__ float4 sh_e[4][4];          // 4 edges x 16 rbf values
    __shared__ int    sh_pair[4];

    const float4* e4   = reinterpret_cast<const float4*>(e_rbf);
    float4*       out4 = reinterpret_cast<float4*>(out);

    for (int base = blockIdx.x * 4; base < E; base += gridDim.x * 4) {
        const int  e     = base + ty;
        const bool valid = (e < E);
        if (valid) {
            if (tx < 4) {
                sh_e[ty][tx] = __ldcs(&e4[e * 4 + tx]);
            } else if (tx == 4) {
                int ns = __ldg(&nbr[2 * e]);
                int nd = __ldg(&nbr[2 * e + 1]);
                sh_pair[ty] = __ldg(&z[ns]) * V + __ldg(&z[nd]);
            }
        }
        __syncthreads();
        if (valid) {
            const float4 E0 = sh_e[ty][0], E1 = sh_e[ty][1];
            const float4 E2 = sh_e[ty][2], E3 = sh_e[ty][3];
            const float er[RBF] = {E0.x, E0.y, E0.z, E0.w,
                                   E1.x, E1.y, E1.z, E1.w,
                                   E2.x, E2.y, E2.z, E2.w,
                                   E3.x, E3.y, E3.z, E3.w};
            float4 acc = __ldg(&g_P12[(long long)sh_pair[ty] * J4 + tx]);
#pragma unroll
            for (int r = 0; r < RBF; ++r) {
                acc.x = fmaf(er[r], w[r].x, acc.x);
                acc.y = fmaf(er[r], w[r].y, acc.y);
                acc.z = fmaf(er[r], w[r].z, acc.z);
                acc.w = fmaf(er[r], w[r].w, acc.w);
            }
            // swish: x * sigmoid(x) = x / (1 + exp(-x))
            acc.x = acc.x / (1.f + __expf(-acc.x));
            acc.y = acc.y / (1.f + __expf(-acc.y));
            acc.z = acc.z / (1.f + __expf(-acc.z));
            acc.w = acc.w / (1.f + __expf(-acc.w));
            __stcs(&out4[(long long)e * J4 + tx], acc);
        }
        __syncthreads();
    }
}

// ---------------------------------------------------------------------------
extern "C" void kernel_launch(void* const* d_in, const int* in_sizes, int n_in,
                              void* d_out, int out_size) {
    const float* e_rbf  = (const float*)d_in[0];
    const int*   z      = (const int*)  d_in[1];
    const int*   nbr    = (const int*)  d_in[2];
    const float* edge_W = (const float*)d_in[3];
    const float* emb    = (const float*)d_in[4];
    const float* dW     = (const float*)d_in[5];
    const float* db     = (const float*)d_in[6];
    float* out = (float*)d_out;

    const int E = in_sizes[0] / RBF;     // 800000
    const int V = in_sizes[4] / D;       // 100

    prep_tables<<<V + RBF, CAT>>>(emb, dW, edge_W, V);
    prep_pairs<<<V * V, CAT>>>(db, V);

    dim3 blk(J4, 4);
    edge_main<<<296, blk>>>(e_rbf, z, nbr, out, E, V);
}

// round 2
// speedup vs baseline: 1.5400x; 1.5400x over previous
#include <cuda_runtime.h>

// EmbeddingBlock: out = swish( [emb[z[s]] | emb[z[d]] | e_rbf@edge_W^T] @ dense_W^T + b )
//
// Factorization (VOCAB=100 distinct embedding rows):
//   P12[vs][vd] = emb[vs]@W[:, :128]^T + emb[vd]@W[:,128:256]^T + b   (100^2 x 272, 10.9 MB, L2-resident)
//   W3eff       = edge_W^T @ W[:,256:272]^T                           (16 x 272, register-resident)
// Per edge: out = swish( P12[pair[e]] + e_rbf[e] @ W3eff )  -> pure memory-bound epilogue.

#define D    128
#define RBF  16
#define CAT  272
#define J4   68          // float4 per 272-wide row
#define VMAX 128
#define EMAX 1048576

__device__ float4 g_W3[RBF * J4];
__device__ float  g_P1[VMAX * CAT];
__device__ float  g_P2[VMAX * CAT];
__device__ float4 g_P12[VMAX * VMAX * J4];   // 17.8 MB reserved, 10.9 MB used
__device__ int    g_pair[EMAX];              // pair index premultiplied by J4

// ---------------------------------------------------------------------------
// Kernel 1: P1, P2 (blocks 0..V-1) and W3eff (blocks V..V+15)
// ---------------------------------------------------------------------------
__global__ void prep_tables(const float* __restrict__ emb,
                            const float* __restrict__ dW,
                            const float* __restrict__ eW,
                            int V) {
    const int bid = blockIdx.x;
    const int j   = threadIdx.x;          // 0..271 output column
    if (bid < V) {
        __shared__ float sh_emb[D];
        if (j < D) sh_emb[j] = emb[bid * D + j];
        __syncthreads();
        const float4* wrow = reinterpret_cast<const float4*>(dW + (long long)j * CAT);
        float a1 = 0.f, a2 = 0.f;
#pragma unroll
        for (int k4 = 0; k4 < D / 4; ++k4) {
            float4 t = wrow[k4];
            a1 = fmaf(sh_emb[4 * k4 + 0], t.x, a1);
            a1 = fmaf(sh_emb[4 * k4 + 1], t.y, a1);
            a1 = fmaf(sh_emb[4 * k4 + 2], t.z, a1);
            a1 = fmaf(sh_emb[4 * k4 + 3], t.w, a1);
        }
#pragma unroll
        for (int k4 = 0; k4 < D / 4; ++k4) {
            float4 t = wrow[D / 4 + k4];
            a2 = fmaf(sh_emb[4 * k4 + 0], t.x, a2);
            a2 = fmaf(sh_emb[4 * k4 + 1], t.y, a2);
            a2 = fmaf(sh_emb[4 * k4 + 2], t.z, a2);
            a2 = fmaf(sh_emb[4 * k4 + 3], t.w, a2);
        }
        g_P1[bid * CAT + j] = a1;
        g_P2[bid * CAT + j] = a2;
    } else {
        const int r = bid - V;             // 0..15
        float a = 0.f;
#pragma unroll
        for (int i = 0; i < RBF; ++i)
            a = fmaf(eW[i * RBF + r], dW[(long long)j * CAT + 2 * D + i], a);
        reinterpret_cast<float*>(g_W3)[r * CAT + j] = a;
    }
}

// ---------------------------------------------------------------------------
// Kernel 2: P12[vs*V+vd] = P1[vs] + P2[vd] + b
// ---------------------------------------------------------------------------
__global__ void prep_pairs(const float* __restrict__ b, int V) {
    const int bid = blockIdx.x;            // vs*V + vd
    const int vs  = bid / V;
    const int vd  = bid - vs * V;
    const int j   = threadIdx.x;           // 0..271
    float val = g_P1[vs * CAT + j] + g_P2[vd * CAT + j] + b[j];
    reinterpret_cast<float*>(g_P12)[(long long)bid * CAT + j] = val;
}

// ---------------------------------------------------------------------------
// Kernel 3: pair index per edge (breaks the nbr->z->P12 dependency chain)
// ---------------------------------------------------------------------------
__global__ void prep_pair_idx(const int* __restrict__ z,
                              const int* __restrict__ nbr,
                              int E, int V) {
    int e = blockIdx.x * blockDim.x + threadIdx.x;
    if (e < E) {
        int2 nn = reinterpret_cast<const int2*>(nbr)[e];
        g_pair[e] = (__ldg(&z[nn.x]) * V + __ldg(&z[nn.y])) * J4;
    }
}

// ---------------------------------------------------------------------------
// Kernel 4: hot epilogue. block = (68, 4): tx = float4 column, ty = edge slot.
// 2 independent edges per thread per iteration; pair indices for the NEXT
// iteration are prefetched; no shared memory, no __syncthreads.
// ---------------------------------------------------------------------------
__global__ void __launch_bounds__(272, 2)
edge_main(const float4* __restrict__ e4, float4* __restrict__ out4, int E) {
    const int tx = threadIdx.x;            // 0..67
    const int ty = threadIdx.y;            // 0..3

    float4 w[RBF];
#pragma unroll
    for (int r = 0; r < RBF; ++r) w[r] = g_W3[r * J4 + tx];

    const int stride = gridDim.x * 8;
    int base = blockIdx.x * 8;
    if (base >= E) return;

    int e0 = base + ty;
    int e1 = base + 4 + ty;
    int p0 = (e0 < E) ? __ldg(&g_pair[e0]) : 0;
    int p1 = (e1 < E) ? __ldg(&g_pair[e1]) : 0;

    for (; base < E; base += stride) {
        const bool v0 = (e0 < E);
        const bool v1 = (e1 < E);

        // ---- issue all long-latency loads for this iteration ----
        float4 acc0 = g_P12[p0 + tx];               // L2, coalesced 512B/warp-row
        float4 acc1 = v1 ? g_P12[p1 + tx] : make_float4(0, 0, 0, 0);

        float4 a0 = __ldg(&e4[(long long)e0 * 4 + 0]);   // warp-broadcast, L1
        float4 a1 = __ldg(&e4[(long long)e0 * 4 + 1]);
        float4 a2 = __ldg(&e4[(long long)e0 * 4 + 2]);
        float4 a3 = __ldg(&e4[(long long)e0 * 4 + 3]);
        long long eb1 = (long long)(v1 ? e1 : e0) * 4;
        float4 b0 = __ldg(&e4[eb1 + 0]);
        float4 b1 = __ldg(&e4[eb1 + 1]);
        float4 b2 = __ldg(&e4[eb1 + 2]);
        float4 b3 = __ldg(&e4[eb1 + 3]);

        // ---- prefetch next iteration's pair indices ----
        int ne0 = e0 + stride, ne1 = e1 + stride;
        int np0 = (ne0 < E) ? __ldg(&g_pair[ne0]) : 0;
        int np1 = (ne1 < E) ? __ldg(&g_pair[ne1]) : 0;

        // ---- edge 0 ----
        {
            const float er[RBF] = {a0.x, a0.y, a0.z, a0.w, a1.x, a1.y, a1.z, a1.w,
                                   a2.x, a2.y, a2.z, a2.w, a3.x, a3.y, a3.z, a3.w};
#pragma unroll
            for (int r = 0; r < RBF; ++r) {
                acc0.x = fmaf(er[r], w[r].x, acc0.x);
                acc0.y = fmaf(er[r], w[r].y, acc0.y);
                acc0.z = fmaf(er[r], w[r].z, acc0.z);
                acc0.w = fmaf(er[r], w[r].w, acc0.w);
            }
            acc0.x = acc0.x / (1.f + __expf(-acc0.x));
            acc0.y = acc0.y / (1.f + __expf(-acc0.y));
            acc0.z = acc0.z / (1.f + __expf(-acc0.z));
            acc0.w = acc0.w / (1.f + __expf(-acc0.w));
            if (v0) __stcs(&out4[(long long)e0 * J4 + tx], acc0);
        }
        // ---- edge 1 ----
        {
            const float er[RBF] = {b0.x, b0.y, b0.z, b0.w, b1.x, b1.y, b1.z, b1.w,
                                   b2.x, b2.y, b2.z, b2.w, b3.x, b3.y, b3.z, b3.w};
#pragma unroll
            for (int r = 0; r < RBF; ++r) {
                acc1.x = fmaf(er[r], w[r].x, acc1.x);
                acc1.y = fmaf(er[r], w[r].y, acc1.y);
                acc1.z = fmaf(er[r], w[r].z, acc1.z);
                acc1.w = fmaf(er[r], w[r].w, acc1.w);
            }
            acc1.x = acc1.x / (1.f + __expf(-acc1.x));
            acc1.y = acc1.y / (1.f + __expf(-acc1.y));
            acc1.z = acc1.z / (1.f + __expf(-acc1.z));
            acc1.w = acc1.w / (1.f + __expf(-acc1.w));
            if (v1) __stcs(&out4[(long long)e1 * J4 + tx], acc1);
        }

        e0 = ne0; e1 = ne1; p0 = np0; p1 = np1;
    }
}

// ---------------------------------------------------------------------------
extern "C" void kernel_launch(void* const* d_in, const int* in_sizes, int n_in,
                              void* d_out, int out_size) {
    const float* e_rbf  = (const float*)d_in[0];
    const int*   z      = (const int*)  d_in[1];
    const int*   nbr    = (const int*)  d_in[2];
    const float* edge_W = (const float*)d_in[3];
    const float* emb    = (const float*)d_in[4];
    const float* dW     = (const float*)d_in[5];
    const float* db     = (const float*)d_in[6];
    float* out = (float*)d_out;

    const int E = in_sizes[0] / RBF;     // 800000
    const int V = in_sizes[4] / D;       // 100

    prep_tables<<<V + RBF, CAT>>>(emb, dW, edge_W, V);
    prep_pairs<<<V * V, CAT>>>(db, V);
    prep_pair_idx<<<(E + 255) / 256, 256>>>(z, nbr, E, V);

    dim3 blk(J4, 4);
    edge_main<<<296, blk>>>(reinterpret_cast<const float4*>(e_rbf),
                            reinterpret_cast<float4*>(out), E);
}